// round 12
// baseline (speedup 1.0000x reference)
#include <cuda_runtime.h>
#include <cuda_fp16.h>
#include <math.h>
#include <stdint.h>

#define NROWS 32768      // B*S
#define FFN   2048
#define EMB   512

// ---------------- scratch ---------------------------------------------------
__device__ __half g_EVh[NROWS * 8];     // 512 KB (fp16 EV)
__device__ __half g_Wh [EMB * FFN];     // 2 MB   (fp16 W2)
__device__ __half g_W1h[FFN * 8];       // 32 KB  (fp16 W1)

// ---------------------------------------------------------------------------
// Kernel 1: quantum circuit collapsed to closed form (verified R1/R2).
// ---------------------------------------------------------------------------
__global__ void ev_kernel(const float* __restrict__ x,
                          const float* __restrict__ params) {
    int row = blockIdx.x * blockDim.x + threadIdx.x;
    if (row >= NROWS) return;
    float z[8];
#pragma unroll
    for (int i = 0; i < 8; i++) {
        float a = params[i * 3 + 0];
        float b = params[i * 3 + 1];
        float c = params[i * 3 + 2];
        float sa, ca, sb, cb, sc, cc;
        sincosf(a, &sa, &ca);
        sincosf(b, &sb, &cb);
        sincosf(c, &sc, &cc);
        float Acoef = ca * cc + sa * sb * sc;
        float Ccoef = cb * sc;
        float sx, cx;
        sincosf(x[row * 8 + i], &sx, &cx);
        z[i] = Acoef * cx - Ccoef * sx;
    }
    float ev[8];
    float pre = z[0];
#pragma unroll
    for (int k = 1; k < 8; k++) { pre *= z[k]; ev[k] = pre; }
    float suf = 1.0f;
#pragma unroll
    for (int k = 7; k >= 1; k--) suf *= z[k];
    ev[0] = suf;
    __align__(16) __half evh[8];
#pragma unroll
    for (int k = 0; k < 8; k++) evh[k] = __float2half(ev[k]);
    *(uint4*)&g_EVh[row * 8] = *(const uint4*)evh;
}

// ---------------------------------------------------------------------------
// Kernel 2: W2 -> fp16
// ---------------------------------------------------------------------------
__global__ void w_half_kernel(const float* __restrict__ W2) {
    int idx = blockIdx.x * blockDim.x + threadIdx.x;
    float2 v = ((const float2*)W2)[idx];
    ((__half2*)g_Wh)[idx] = __floats2half2_rn(v.x, v.y);
}

// ---------------------------------------------------------------------------
// Kernel 3: W1 -> fp16
// ---------------------------------------------------------------------------
__global__ void w1_half_kernel(const float* __restrict__ W1) {
    int r = blockIdx.x * blockDim.x + threadIdx.x;
    float4 v0 = *(const float4*)&W1[r * 8];
    float4 v1 = *(const float4*)&W1[r * 8 + 4];
    __align__(16) __half h[8];
    h[0] = __float2half(v0.x); h[1] = __float2half(v0.y);
    h[2] = __float2half(v0.z); h[3] = __float2half(v0.w);
    h[4] = __float2half(v1.x); h[5] = __float2half(v1.y);
    h[6] = __float2half(v1.z); h[7] = __float2half(v1.w);
    *(uint4*)&g_W1h[r * 8] = *(const uint4*)h;
}

// ---------------------------------------------------------------------------
// Kernel 4 (fused, pipelined): OUT = relu(EV@W1^T + b1) @ W2^T + b2.
// A fragments produced on tensor core (m16n8k8 H-mma + relu/pack), generated
// ONE k16 CHUNK AHEAD in a double buffer so the cvt chain hides behind the
// current chunk's main mmas.  CTA 128x64, BK=64, 4 warps, 3-stage cp.async.
// ---------------------------------------------------------------------------
#define BM 128
#define BN 64
#define BK 64
#define NT (FFN / BK)             // 32
#define STG 8192                  // B tile only: 64 rows x 128B

#define CP16(dst, src) \
    asm volatile("cp.async.cg.shared.global [%0], [%1], 16;\n" :: "r"(dst), "l"(src))

__device__ __forceinline__ void ldsm4(unsigned* r, unsigned a) {
    asm volatile("ldmatrix.sync.aligned.m8n8.x4.shared.b16 {%0,%1,%2,%3}, [%4];"
                 : "=r"(r[0]), "=r"(r[1]), "=r"(r[2]), "=r"(r[3]) : "r"(a));
}

__device__ __forceinline__ void mma16816(float* c, const unsigned* a, const unsigned* b) {
    asm volatile("mma.sync.aligned.m16n8k16.row.col.f32.f16.f16.f32 "
                 "{%0,%1,%2,%3}, {%4,%5,%6,%7}, {%8,%9}, {%0,%1,%2,%3};"
                 : "+f"(c[0]), "+f"(c[1]), "+f"(c[2]), "+f"(c[3])
                 : "r"(a[0]), "r"(a[1]), "r"(a[2]), "r"(a[3]), "r"(b[0]), "r"(b[1]));
}

__device__ __forceinline__ void mma16808(float* c, const unsigned* a, unsigned b) {
    asm volatile("mma.sync.aligned.m16n8k8.row.col.f32.f16.f16.f32 "
                 "{%0,%1,%2,%3}, {%4,%5}, {%6}, {%0,%1,%2,%3};"
                 : "+f"(c[0]), "+f"(c[1]), "+f"(c[2]), "+f"(c[3])
                 : "r"(a[0]), "r"(a[1]), "r"(b));
}

__device__ __forceinline__ unsigned rpack(float x, float y) {
    __half2 h = __floats2half2_rn(x, y);
    h = __hmax2(h, __floats2half2_rn(0.0f, 0.0f));
    return reinterpret_cast<unsigned&>(h);
}

// 128B rows, 8 chunks of 16B, full SW128 swizzle
__device__ __forceinline__ unsigned swz(int row, int ch) {
    return (unsigned)(row * 128 + ((ch ^ (row & 7)) << 4));
}

__device__ __forceinline__ void load_stage(unsigned st, int bn, int tid, int k0) {
#pragma unroll
    for (int i = 0; i < 4; i++) {
        int id = tid + (i << 7);
        int r = id >> 3, c = id & 7;
        size_t g = (size_t)(bn + r) * FFN + k0 + c * 8;
        CP16(st + swz(r, c), g_Wh + g);
    }
}

// Generate A fragments (relu(EV@W1^T+b1), m16k16 operand layout) for k16
// chunk at column offset ko.  Pure register/L1 work; no smem.
__device__ __forceinline__ void gen_afr(unsigned afr[4][4],
                                        const unsigned evf[4][2],
                                        const float* __restrict__ b1,
                                        int ko, int lane) {
    unsigned w1a = *(const unsigned*)&g_W1h[(ko +     (lane >> 2)) * 8 + 2 * (lane & 3)];
    unsigned w1b = *(const unsigned*)&g_W1h[(ko + 8 + (lane >> 2)) * 8 + 2 * (lane & 3)];
    float2 bva = *(const float2*)&b1[ko +     2 * (lane & 3)];
    float2 bvb = *(const float2*)&b1[ko + 8 + 2 * (lane & 3)];
#pragma unroll
    for (int mf = 0; mf < 4; mf++) {
        float h0[4] = {bva.x, bva.y, bva.x, bva.y};
        float h1[4] = {bvb.x, bvb.y, bvb.x, bvb.y};
        mma16808(h0, evf[mf], w1a);
        mma16808(h1, evf[mf], w1b);
        afr[mf][0] = rpack(h0[0], h0[1]);
        afr[mf][1] = rpack(h0[2], h0[3]);
        afr[mf][2] = rpack(h1[0], h1[1]);
        afr[mf][3] = rpack(h1[2], h1[3]);
    }
}

__global__ void __launch_bounds__(128, 3)
mma_gemm(const float* __restrict__ b1, const float* __restrict__ bias,
         float* __restrict__ C) {
    __shared__ __align__(128) unsigned char smem[3 * STG];
    const int tid  = threadIdx.x;
    const int warp = tid >> 5, lane = tid & 31;
    const int wm = warp & 1;
    const int wn = warp >> 1;
    const int bm = blockIdx.y * BM, bn = blockIdx.x * BN;
    const unsigned sbase = (unsigned)__cvta_generic_to_shared(smem);

    // EV A-fragments (m16k8), k-invariant
    unsigned evf[4][2];
#pragma unroll
    for (int mf = 0; mf < 4; mf++) {
        int r = bm + wm * 64 + mf * 16 + (lane >> 2);
        evf[mf][0] = *(const unsigned*)&g_EVh[r * 8 + 2 * (lane & 3)];
        evf[mf][1] = *(const unsigned*)&g_EVh[(r + 8) * 8 + 2 * (lane & 3)];
    }

    float acc[4][4][4];
#pragma unroll
    for (int i = 0; i < 4; i++)
#pragma unroll
        for (int j = 0; j < 4; j++)
#pragma unroll
            for (int k = 0; k < 4; k++) acc[i][j][k] = 0.0f;

    load_stage(sbase,       bn, tid, 0);
    asm volatile("cp.async.commit_group;\n");
    load_stage(sbase + STG, bn, tid, BK);
    asm volatile("cp.async.commit_group;\n");

    // A-fragment double buffer, primed with chunk 0
    unsigned afr[2][4][4];
    gen_afr(afr[0], evf, b1, 0, lane);
    int cur = 0;

    for (int t = 0; t < NT; t++) {
        if (t + 1 < NT) asm volatile("cp.async.wait_group 1;\n" ::: "memory");
        else            asm volatile("cp.async.wait_group 0;\n" ::: "memory");
        __syncthreads();

        if (t + 2 < NT) {
            load_stage(sbase + ((t + 2) % 3) * STG, bn, tid, (t + 2) * BK);
            asm volatile("cp.async.commit_group;\n");
        }

        unsigned st = sbase + (t % 3) * STG;
#pragma unroll
        for (int kk = 0; kk < 4; kk++) {
            // main-GEMM B fragments for this chunk
            unsigned bfr[2][4];
#pragma unroll
            for (int nb = 0; nb < 2; nb++) {
                int n  = wn * 32 + nb * 16 + (lane & 7) + ((lane >> 4) & 1) * 8;
                int ch = kk * 2 + ((lane >> 3) & 1);
                ldsm4(bfr[nb], st + swz(n, ch));
            }

            // generate NEXT chunk's A fragments (hides cvt behind main mmas)
            int nko = t * BK + kk * 16 + 16;
            if (nko < FFN)
                gen_afr(afr[cur ^ 1], evf, b1, nko, lane);

            // main mmas with CURRENT chunk's A fragments
#pragma unroll
            for (int mf = 0; mf < 4; mf++)
#pragma unroll
                for (int nf = 0; nf < 4; nf++)
                    mma16816(acc[mf][nf], afr[cur][mf], &bfr[nf >> 1][(nf & 1) * 2]);

            cur ^= 1;
        }
    }

    // epilogue: add bias b2
#pragma unroll
    for (int mf = 0; mf < 4; mf++) {
        int r0 = bm + wm * 64 + mf * 16 + (lane >> 2);
#pragma unroll
        for (int nf = 0; nf < 4; nf++) {
            int cc = bn + wn * 32 + nf * 8 + (lane & 3) * 2;
            float2 b2 = *(const float2*)&bias[cc];
            float2 v0 = make_float2(acc[mf][nf][0] + b2.x, acc[mf][nf][1] + b2.y);
            float2 v1 = make_float2(acc[mf][nf][2] + b2.x, acc[mf][nf][3] + b2.y);
            *(float2*)&C[(size_t)r0 * EMB + cc]       = v0;
            *(float2*)&C[(size_t)(r0 + 8) * EMB + cc] = v1;
        }
    }
}

// ---------------------------------------------------------------------------
extern "C" void kernel_launch(void* const* d_in, const int* in_sizes, int n_in,
                              void* d_out, int out_size) {
    const float* x      = (const float*)d_in[0];  // [16,2048,8]
    const float* params = (const float*)d_in[1];  // [8,3]
    const float* W1     = (const float*)d_in[2];  // [2048,8]
    const float* b1     = (const float*)d_in[3];  // [2048]
    const float* W2     = (const float*)d_in[4];  // [512,2048]
    const float* b2     = (const float*)d_in[5];  // [512]
    float* out = (float*)d_out;                   // [16,2048,512]

    w_half_kernel<<<(EMB * (FFN / 2)) / 256, 256>>>(W2);
    w1_half_kernel<<<FFN / 256, 256>>>(W1);
    ev_kernel<<<NROWS / 256, 256>>>(x, params);
    mma_gemm<<<dim3(EMB / BN, NROWS / BM), 128>>>(b1, b2, out);
}

// round 13
// speedup vs baseline: 1.2308x; 1.2308x over previous
#include <cuda_runtime.h>
#include <cuda_fp16.h>
#include <math.h>
#include <stdint.h>

#define NROWS 32768      // B*S
#define FFN   2048
#define EMB   512

// ---------------- scratch ---------------------------------------------------
__device__ float  g_EV[NROWS * 8];                 // 1 MB
__device__ __half g_H[(size_t)NROWS * FFN];        // 128 MB (fp16 of H)
__device__ __half g_Wh[EMB * FFN];                 // 2 MB  (fp16 of W2)

// ---------------------------------------------------------------------------
// Kernel 1: quantum circuit collapsed to closed form (verified R1/R2).
// ---------------------------------------------------------------------------
__global__ void ev_kernel(const float* __restrict__ x,
                          const float* __restrict__ params) {
    int row = blockIdx.x * blockDim.x + threadIdx.x;
    if (row >= NROWS) return;
    float z[8];
#pragma unroll
    for (int i = 0; i < 8; i++) {
        float a = params[i * 3 + 0];
        float b = params[i * 3 + 1];
        float c = params[i * 3 + 2];
        float sa, ca, sb, cb, sc, cc;
        sincosf(a, &sa, &ca);
        sincosf(b, &sb, &cb);
        sincosf(c, &sc, &cc);
        float Acoef = ca * cc + sa * sb * sc;
        float Ccoef = cb * sc;
        float sx, cx;
        sincosf(x[row * 8 + i], &sx, &cx);
        z[i] = Acoef * cx - Ccoef * sx;
    }
    float ev[8];
    float pre = z[0];
#pragma unroll
    for (int k = 1; k < 8; k++) { pre *= z[k]; ev[k] = pre; }
    float suf = 1.0f;
#pragma unroll
    for (int k = 7; k >= 1; k--) suf *= z[k];
    ev[0] = suf;
    float4* out = (float4*)&g_EV[row * 8];
    out[0] = make_float4(ev[0], ev[1], ev[2], ev[3]);
    out[1] = make_float4(ev[4], ev[5], ev[6], ev[7]);
}

// ---------------------------------------------------------------------------
// Kernel 2 (v3): H = relu(EV @ W1^T + b1) -> fp16.
// Thread owns 4 columns (W1 in 32 regs), loops 64 rows; STG.64 stores.
// ---------------------------------------------------------------------------
#define HROWS 64
__global__ void __launch_bounds__(256)
h_half_kernel(const float* __restrict__ W1, const float* __restrict__ b1) {
    int c0 = blockIdx.x * 1024 + threadIdx.x * 4;   // four columns
    int r0 = blockIdx.y * HROWS;
    float4 w0[4], w1[4];
    float bb[4];
#pragma unroll
    for (int j = 0; j < 4; j++) {
        w0[j] = *(const float4*)&W1[(c0 + j) * 8];
        w1[j] = *(const float4*)&W1[(c0 + j) * 8 + 4];
        bb[j] = b1[c0 + j];
    }
#pragma unroll 4
    for (int r = r0; r < r0 + HROWS; r++) {
        float4 e0 = *(const float4*)&g_EV[r * 8];
        float4 e1 = *(const float4*)&g_EV[r * 8 + 4];
        float h[4];
#pragma unroll
        for (int j = 0; j < 4; j++) {
            h[j] = bb[j]
                 + e0.x * w0[j].x + e0.y * w0[j].y + e0.z * w0[j].z + e0.w * w0[j].w
                 + e1.x * w1[j].x + e1.y * w1[j].y + e1.z * w1[j].z + e1.w * w1[j].w;
        }
        __half2 p0 = __floats2half2_rn(fmaxf(h[0], 0.0f), fmaxf(h[1], 0.0f));
        __half2 p1 = __floats2half2_rn(fmaxf(h[2], 0.0f), fmaxf(h[3], 0.0f));
        uint2 st;
        st.x = reinterpret_cast<unsigned&>(p0);
        st.y = reinterpret_cast<unsigned&>(p1);
        *(uint2*)&g_H[(size_t)r * FFN + c0] = st;
    }
}

// ---------------------------------------------------------------------------
// Kernel 3: W2 -> fp16
// ---------------------------------------------------------------------------
__global__ void w_half_kernel(const float* __restrict__ W2) {
    int idx = blockIdx.x * blockDim.x + threadIdx.x;   // [0, EMB*FFN/2)
    float2 v = ((const float2*)W2)[idx];
    ((__half2*)g_Wh)[idx] = __floats2half2_rn(v.x, v.y);
}

// ---------------------------------------------------------------------------
// Kernel 4: OUT = H @ W2^T + b2, mma.sync fp16 single pass, fp32 acc.
// CTA 128x64, BK=64, 4 warps (2x2, warp tile 64x32), 3-stage cp.async,
// 72KB dynamic smem, 3 CTAs/SM.  (R10-proven, byte-identical.)
// ---------------------------------------------------------------------------
#define BM 128
#define BN 64
#define BK 64
#define NT (FFN / BK)             // 32
#define STG 24576                 // A 0 (16384), B 16384 (8192)
#define SMEM_TOTAL (3 * STG)      // 73728

#define CP16(dst, src) \
    asm volatile("cp.async.cg.shared.global [%0], [%1], 16;\n" :: "r"(dst), "l"(src))

__device__ __forceinline__ void ldsm4(unsigned* r, unsigned a) {
    asm volatile("ldmatrix.sync.aligned.m8n8.x4.shared.b16 {%0,%1,%2,%3}, [%4];"
                 : "=r"(r[0]), "=r"(r[1]), "=r"(r[2]), "=r"(r[3]) : "r"(a));
}

__device__ __forceinline__ void mma16816(float* c, const unsigned* a, const unsigned* b) {
    asm volatile("mma.sync.aligned.m16n8k16.row.col.f32.f16.f16.f32 "
                 "{%0,%1,%2,%3}, {%4,%5,%6,%7}, {%8,%9}, {%0,%1,%2,%3};"
                 : "+f"(c[0]), "+f"(c[1]), "+f"(c[2]), "+f"(c[3])
                 : "r"(a[0]), "r"(a[1]), "r"(a[2]), "r"(a[3]), "r"(b[0]), "r"(b[1]));
}

// 128B rows, 8 chunks of 16B, full SW128 swizzle
__device__ __forceinline__ unsigned swz(int row, int ch) {
    return (unsigned)(row * 128 + ((ch ^ (row & 7)) << 4));
}

__device__ __forceinline__ void load_stage(unsigned st, int bm, int bn, int tid, int k0) {
#pragma unroll
    for (int i = 0; i < 8; i++) {               // A: 1024 chunks of 16B
        int id = tid + (i << 7);
        int r = id >> 3, c = id & 7;
        size_t g = (size_t)(bm + r) * FFN + k0 + c * 8;
        CP16(st + swz(r, c), g_H + g);
    }
#pragma unroll
    for (int i = 0; i < 4; i++) {               // B: 512 chunks of 16B
        int id = tid + (i << 7);
        int r = id >> 3, c = id & 7;
        size_t g = (size_t)(bn + r) * FFN + k0 + c * 8;
        CP16(st + 16384 + swz(r, c), g_Wh + g);
    }
}

__global__ void __launch_bounds__(128, 3)
mma_gemm(const float* __restrict__ bias, float* __restrict__ C) {
    extern __shared__ __align__(128) unsigned char smem[];
    const int tid  = threadIdx.x;
    const int warp = tid >> 5, lane = tid & 31;
    const int wm = warp & 1;                 // 2 m-groups of 64 rows
    const int wn = warp >> 1;                // 2 n-groups of 32 cols
    const int bm = blockIdx.y * BM, bn = blockIdx.x * BN;
    const unsigned sbase = (unsigned)__cvta_generic_to_shared(smem);

    float acc[4][4][4];                      // [mf][nf][frag]
#pragma unroll
    for (int i = 0; i < 4; i++)
#pragma unroll
        for (int j = 0; j < 4; j++)
#pragma unroll
            for (int k = 0; k < 4; k++) acc[i][j][k] = 0.0f;

    load_stage(sbase,       bm, bn, tid, 0);
    asm volatile("cp.async.commit_group;\n");
    load_stage(sbase + STG, bm, bn, tid, BK);
    asm volatile("cp.async.commit_group;\n");

    for (int t = 0; t < NT; t++) {
        if (t + 1 < NT) asm volatile("cp.async.wait_group 1;\n" ::: "memory");
        else            asm volatile("cp.async.wait_group 0;\n" ::: "memory");
        __syncthreads();          // single barrier per stage (3-stage ring)

        if (t + 2 < NT) {
            load_stage(sbase + ((t + 2) % 3) * STG, bm, bn, tid, (t + 2) * BK);
            asm volatile("cp.async.commit_group;\n");
        }

        unsigned st = sbase + (t % 3) * STG;
#pragma unroll
        for (int kk = 0; kk < 4; kk++) {     // four k16 chunks of BK=64
            unsigned ah[4][4], bh[2][4];
#pragma unroll
            for (int mf = 0; mf < 4; mf++) {     // A frags: m64 x k16
                int r  = wm * 64 + mf * 16 + (lane & 15);
                int ch = kk * 2 + (lane >> 4);
                ldsm4(ah[mf], st + swz(r, ch));
            }
#pragma unroll
            for (int nb = 0; nb < 2; nb++) {     // B frags: n32
                int n  = wn * 32 + nb * 16 + (lane & 7) + ((lane >> 4) & 1) * 8;
                int ch = kk * 2 + ((lane >> 3) & 1);
                ldsm4(bh[nb], st + 16384 + swz(n, ch));
            }
#pragma unroll
            for (int mf = 0; mf < 4; mf++)
#pragma unroll
                for (int nf = 0; nf < 4; nf++)
                    mma16816(acc[mf][nf], ah[mf], &bh[nf >> 1][(nf & 1) * 2]);
        }
    }

    // epilogue: add bias
#pragma unroll
    for (int mf = 0; mf < 4; mf++) {
        int r0 = bm + wm * 64 + mf * 16 + (lane >> 2);
#pragma unroll
        for (int nf = 0; nf < 4; nf++) {
            int cc = bn + wn * 32 + nf * 8 + (lane & 3) * 2;
            float2 b2 = *(const float2*)&bias[cc];
            float2 v0 = make_float2(acc[mf][nf][0] + b2.x, acc[mf][nf][1] + b2.y);
            float2 v1 = make_float2(acc[mf][nf][2] + b2.x, acc[mf][nf][3] + b2.y);
            *(float2*)&C[(size_t)r0 * EMB + cc]       = v0;
            *(float2*)&C[(size_t)(r0 + 8) * EMB + cc] = v1;
        }
    }
}

// ---------------------------------------------------------------------------
extern "C" void kernel_launch(void* const* d_in, const int* in_sizes, int n_in,
                              void* d_out, int out_size) {
    const float* x      = (const float*)d_in[0];  // [16,2048,8]
    const float* params = (const float*)d_in[1];  // [8,3]
    const float* W1     = (const float*)d_in[2];  // [2048,8]
    const float* b1     = (const float*)d_in[3];  // [2048]
    const float* W2     = (const float*)d_in[4];  // [512,2048]
    const float* b2     = (const float*)d_in[5];  // [512]
    float* out = (float*)d_out;                   // [16,2048,512]

    cudaFuncSetAttribute(mma_gemm, cudaFuncAttributeMaxDynamicSharedMemorySize,
                         SMEM_TOTAL);

    w_half_kernel<<<(EMB * (FFN / 2)) / 256, 256>>>(W2);
    ev_kernel<<<NROWS / 256, 256>>>(x, params);
    h_half_kernel<<<dim3(FFN / 1024, NROWS / HROWS), 256>>>(W1, b1);
    mma_gemm<<<dim3(EMB / BN, NROWS / BM), 128, SMEM_TOTAL>>>(b2, out);
}

// round 14
// speedup vs baseline: 1.2661x; 1.0287x over previous
#include <cuda_runtime.h>
#include <cuda_fp16.h>
#include <math.h>
#include <stdint.h>

#define NROWS 32768      // B*S
#define FFN   2048
#define EMB   512

// ---------------- scratch ---------------------------------------------------
__device__ float  g_EV[NROWS * 8];                 // 1 MB
__device__ __half g_H[(size_t)NROWS * FFN];        // 128 MB (fp16 of H)
__device__ __half g_Wh[EMB * FFN];                 // 2 MB  (fp16 of W2)

// ---------------------------------------------------------------------------
// Kernel 1: quantum circuit collapsed to closed form (verified R1/R2).
// ---------------------------------------------------------------------------
__global__ void ev_kernel(const float* __restrict__ x,
                          const float* __restrict__ params) {
    int row = blockIdx.x * blockDim.x + threadIdx.x;
    if (row >= NROWS) return;
    float z[8];
#pragma unroll
    for (int i = 0; i < 8; i++) {
        float a = params[i * 3 + 0];
        float b = params[i * 3 + 1];
        float c = params[i * 3 + 2];
        float sa, ca, sb, cb, sc, cc;
        sincosf(a, &sa, &ca);
        sincosf(b, &sb, &cb);
        sincosf(c, &sc, &cc);
        float Acoef = ca * cc + sa * sb * sc;
        float Ccoef = cb * sc;
        float sx, cx;
        sincosf(x[row * 8 + i], &sx, &cx);
        z[i] = Acoef * cx - Ccoef * sx;
    }
    float ev[8];
    float pre = z[0];
#pragma unroll
    for (int k = 1; k < 8; k++) { pre *= z[k]; ev[k] = pre; }
    float suf = 1.0f;
#pragma unroll
    for (int k = 7; k >= 1; k--) suf *= z[k];
    ev[0] = suf;
    float4* out = (float4*)&g_EV[row * 8];
    out[0] = make_float4(ev[0], ev[1], ev[2], ev[3]);
    out[1] = make_float4(ev[4], ev[5], ev[6], ev[7]);
}

// ---------------------------------------------------------------------------
// Kernel 2: H = relu(EV @ W1^T + b1) -> fp16.  (R13: 4 cols/thread, STG.64)
// ---------------------------------------------------------------------------
#define HROWS 64
__global__ void __launch_bounds__(256)
h_half_kernel(const float* __restrict__ W1, const float* __restrict__ b1) {
    int c0 = blockIdx.x * 1024 + threadIdx.x * 4;
    int r0 = blockIdx.y * HROWS;
    float4 w0[4], w1[4];
    float bb[4];
#pragma unroll
    for (int j = 0; j < 4; j++) {
        w0[j] = *(const float4*)&W1[(c0 + j) * 8];
        w1[j] = *(const float4*)&W1[(c0 + j) * 8 + 4];
        bb[j] = b1[c0 + j];
    }
#pragma unroll 4
    for (int r = r0; r < r0 + HROWS; r++) {
        float4 e0 = *(const float4*)&g_EV[r * 8];
        float4 e1 = *(const float4*)&g_EV[r * 8 + 4];
        float h[4];
#pragma unroll
        for (int j = 0; j < 4; j++) {
            h[j] = bb[j]
                 + e0.x * w0[j].x + e0.y * w0[j].y + e0.z * w0[j].z + e0.w * w0[j].w
                 + e1.x * w1[j].x + e1.y * w1[j].y + e1.z * w1[j].z + e1.w * w1[j].w;
        }
        __half2 p0 = __floats2half2_rn(fmaxf(h[0], 0.0f), fmaxf(h[1], 0.0f));
        __half2 p1 = __floats2half2_rn(fmaxf(h[2], 0.0f), fmaxf(h[3], 0.0f));
        uint2 st;
        st.x = reinterpret_cast<unsigned&>(p0);
        st.y = reinterpret_cast<unsigned&>(p1);
        *(uint2*)&g_H[(size_t)r * FFN + c0] = st;
    }
}

// ---------------------------------------------------------------------------
// Kernel 3: W2 -> fp16
// ---------------------------------------------------------------------------
__global__ void w_half_kernel(const float* __restrict__ W2) {
    int idx = blockIdx.x * blockDim.x + threadIdx.x;
    float2 v = ((const float2*)W2)[idx];
    ((__half2*)g_Wh)[idx] = __floats2half2_rn(v.x, v.y);
}

// ---------------------------------------------------------------------------
// Kernel 4: OUT = H @ W2^T + b2, mma.sync fp16 single pass, fp32 acc.
// CTA 128x128, BK=64, 4 warps (2x2, warp tile 64x64), 3-stage cp.async,
// 96KB dynamic smem, 2 CTAs/SM.  (1.5x less smem traffic per MAC vs R13.)
// ---------------------------------------------------------------------------
#define BM 128
#define BN 128
#define BK 64
#define NT (FFN / BK)             // 32
#define STG 32768                 // A 0 (16384), B 16384 (16384)
#define SMEM_TOTAL (3 * STG)      // 98304

#define CP16(dst, src) \
    asm volatile("cp.async.cg.shared.global [%0], [%1], 16;\n" :: "r"(dst), "l"(src))

__device__ __forceinline__ void ldsm4(unsigned* r, unsigned a) {
    asm volatile("ldmatrix.sync.aligned.m8n8.x4.shared.b16 {%0,%1,%2,%3}, [%4];"
                 : "=r"(r[0]), "=r"(r[1]), "=r"(r[2]), "=r"(r[3]) : "r"(a));
}

__device__ __forceinline__ void mma16816(float* c, const unsigned* a, const unsigned* b) {
    asm volatile("mma.sync.aligned.m16n8k16.row.col.f32.f16.f16.f32 "
                 "{%0,%1,%2,%3}, {%4,%5,%6,%7}, {%8,%9}, {%0,%1,%2,%3};"
                 : "+f"(c[0]), "+f"(c[1]), "+f"(c[2]), "+f"(c[3])
                 : "r"(a[0]), "r"(a[1]), "r"(a[2]), "r"(a[3]), "r"(b[0]), "r"(b[1]));
}

// 128B rows, 8 chunks of 16B, full SW128 swizzle
__device__ __forceinline__ unsigned swz(int row, int ch) {
    return (unsigned)(row * 128 + ((ch ^ (row & 7)) << 4));
}

__device__ __forceinline__ void load_stage(unsigned st, int bm, int bn, int tid, int k0) {
#pragma unroll
    for (int i = 0; i < 8; i++) {               // A: 1024 chunks of 16B
        int id = tid + (i << 7);
        int r = id >> 3, c = id & 7;
        size_t g = (size_t)(bm + r) * FFN + k0 + c * 8;
        CP16(st + swz(r, c), g_H + g);
    }
#pragma unroll
    for (int i = 0; i < 8; i++) {               // B: 1024 chunks of 16B
        int id = tid + (i << 7);
        int r = id >> 3, c = id & 7;
        size_t g = (size_t)(bn + r) * FFN + k0 + c * 8;
        CP16(st + 16384 + swz(r, c), g_Wh + g);
    }
}

__global__ void __launch_bounds__(128, 2)
mma_gemm(const float* __restrict__ bias, float* __restrict__ C) {
    extern __shared__ __align__(128) unsigned char smem[];
    const int tid  = threadIdx.x;
    const int warp = tid >> 5, lane = tid & 31;
    const int wm = warp & 1;                 // 2 m-groups of 64 rows
    const int wn = warp >> 1;                // 2 n-groups of 64 cols
    const int bm = blockIdx.y * BM, bn = blockIdx.x * BN;
    const unsigned sbase = (unsigned)__cvta_generic_to_shared(smem);

    float acc[4][8][4];                      // [mf][nf][frag]
#pragma unroll
    for (int i = 0; i < 4; i++)
#pragma unroll
        for (int j = 0; j < 8; j++)
#pragma unroll
            for (int k = 0; k < 4; k++) acc[i][j][k] = 0.0f;

    load_stage(sbase,       bm, bn, tid, 0);
    asm volatile("cp.async.commit_group;\n");
    load_stage(sbase + STG, bm, bn, tid, BK);
    asm volatile("cp.async.commit_group;\n");

    for (int t = 0; t < NT; t++) {
        if (t + 1 < NT) asm volatile("cp.async.wait_group 1;\n" ::: "memory");
        else            asm volatile("cp.async.wait_group 0;\n" ::: "memory");
        __syncthreads();          // single barrier per stage (3-stage ring)

        if (t + 2 < NT) {
            load_stage(sbase + ((t + 2) % 3) * STG, bm, bn, tid, (t + 2) * BK);
            asm volatile("cp.async.commit_group;\n");
        }

        unsigned st = sbase + (t % 3) * STG;
#pragma unroll
        for (int kk = 0; kk < 4; kk++) {     // four k16 chunks of BK=64
            unsigned ah[4][4], bh[4][4];
#pragma unroll
            for (int mf = 0; mf < 4; mf++) {     // A frags: m64 x k16
                int r  = wm * 64 + mf * 16 + (lane & 15);
                int ch = kk * 2 + (lane >> 4);
                ldsm4(ah[mf], st + swz(r, ch));
            }
#pragma unroll
            for (int nb = 0; nb < 4; nb++) {     // B frags: n64
                int n  = wn * 64 + nb * 16 + (lane & 7) + ((lane >> 4) & 1) * 8;
                int ch = kk * 2 + ((lane >> 3) & 1);
                ldsm4(bh[nb], st + 16384 + swz(n, ch));
            }
#pragma unroll
            for (int mf = 0; mf < 4; mf++)
#pragma unroll
                for (int nf = 0; nf < 8; nf++)
                    mma16816(acc[mf][nf], ah[mf], &bh[nf >> 1][(nf & 1) * 2]);
        }
    }

    // epilogue: add bias
#pragma unroll
    for (int mf = 0; mf < 4; mf++) {
        int r0 = bm + wm * 64 + mf * 16 + (lane >> 2);
#pragma unroll
        for (int nf = 0; nf < 8; nf++) {
            int cc = bn + wn * 64 + nf * 8 + (lane & 3) * 2;
            float2 b2 = *(const float2*)&bias[cc];
            float2 v0 = make_float2(acc[mf][nf][0] + b2.x, acc[mf][nf][1] + b2.y);
            float2 v1 = make_float2(acc[mf][nf][2] + b2.x, acc[mf][nf][3] + b2.y);
            *(float2*)&C[(size_t)r0 * EMB + cc]       = v0;
            *(float2*)&C[(size_t)(r0 + 8) * EMB + cc] = v1;
        }
    }
}

// ---------------------------------------------------------------------------
extern "C" void kernel_launch(void* const* d_in, const int* in_sizes, int n_in,
                              void* d_out, int out_size) {
    const float* x      = (const float*)d_in[0];  // [16,2048,8]
    const float* params = (const float*)d_in[1];  // [8,3]
    const float* W1     = (const float*)d_in[2];  // [2048,8]
    const float* b1     = (const float*)d_in[3];  // [2048]
    const float* W2     = (const float*)d_in[4];  // [512,2048]
    const float* b2     = (const float*)d_in[5];  // [512]
    float* out = (float*)d_out;                   // [16,2048,512]

    cudaFuncSetAttribute(mma_gemm, cudaFuncAttributeMaxDynamicSharedMemorySize,
                         SMEM_TOTAL);

    w_half_kernel<<<(EMB * (FFN / 2)) / 256, 256>>>(W2);
    ev_kernel<<<NROWS / 256, 256>>>(x, params);
    h_half_kernel<<<dim3(FFN / 1024, NROWS / HROWS), 256>>>(W1, b1);
    mma_gemm<<<dim3(EMB / BN, NROWS / BM), 128, SMEM_TOTAL>>>(b2, out);
}

// round 15
// speedup vs baseline: 1.3988x; 1.1048x over previous
#include <cuda_runtime.h>
#include <cuda_fp16.h>
#include <math.h>
#include <stdint.h>

#define NROWS 32768      // B*S
#define FFN   2048
#define EMB   512

// ---------------- scratch ---------------------------------------------------
__device__ __half g_H[(size_t)NROWS * FFN];        // 128 MB (fp16 of H)
__device__ __half g_Wh[EMB * FFN];                 // 2 MB  (fp16 of W2)

// ---------------------------------------------------------------------------
// Kernel 1 (fused): EV (closed-form circuit, verified R1/R2) + 
// H = relu(EV @ W1^T + b1) -> fp16.  Redundancy-1: one block owns 64 rows x
// ALL 2048 columns; EV computed once into smem, W1 cached in regs (8 cols/thr).
// ---------------------------------------------------------------------------
#define HROWS 64
__global__ void __launch_bounds__(256)
h_fused_kernel(const float* __restrict__ x, const float* __restrict__ params,
               const float* __restrict__ W1, const float* __restrict__ b1) {
    __shared__ float sA[8], sC[8];
    __shared__ float sEV[HROWS][8];
    const int tid = threadIdx.x;
    const int r0  = blockIdx.x * HROWS;

    if (tid < 8) {
        float a = params[tid * 3 + 0];
        float b = params[tid * 3 + 1];
        float c = params[tid * 3 + 2];
        float sa, ca, sb, cb, sc, cc;
        sincosf(a, &sa, &ca);
        sincosf(b, &sb, &cb);
        sincosf(c, &sc, &cc);
        sA[tid] = ca * cc + sa * sb * sc;
        sC[tid] = cb * sc;
    }
    __syncthreads();

    if (tid < HROWS) {
        int row = r0 + tid;
        float z[8];
#pragma unroll
        for (int i = 0; i < 8; i++) {
            float sx, cx;
            sincosf(x[row * 8 + i], &sx, &cx);
            z[i] = sA[i] * cx - sC[i] * sx;
        }
        float ev[8];
        float pre = z[0];
#pragma unroll
        for (int k = 1; k < 8; k++) { pre *= z[k]; ev[k] = pre; }
        float suf = 1.0f;
#pragma unroll
        for (int k = 7; k >= 1; k--) suf *= z[k];
        ev[0] = suf;
#pragma unroll
        for (int k = 0; k < 8; k++) sEV[tid][k] = ev[k];
    }

    // W1 for this thread's 8 columns, cached in registers
    const int c0 = tid * 8;
    float4 w0[8], w1[8];
    float bb[8];
#pragma unroll
    for (int j = 0; j < 8; j++) {
        w0[j] = *(const float4*)&W1[(c0 + j) * 8];
        w1[j] = *(const float4*)&W1[(c0 + j) * 8 + 4];
        bb[j] = b1[c0 + j];
    }
    __syncthreads();

#pragma unroll 2
    for (int r = 0; r < HROWS; r++) {
        float4 e0 = *(const float4*)&sEV[r][0];
        float4 e1 = *(const float4*)&sEV[r][4];
        float h[8];
#pragma unroll
        for (int j = 0; j < 8; j++) {
            h[j] = bb[j]
                 + e0.x * w0[j].x + e0.y * w0[j].y + e0.z * w0[j].z + e0.w * w0[j].w
                 + e1.x * w1[j].x + e1.y * w1[j].y + e1.z * w1[j].z + e1.w * w1[j].w;
        }
        __half2 p0 = __floats2half2_rn(fmaxf(h[0], 0.0f), fmaxf(h[1], 0.0f));
        __half2 p1 = __floats2half2_rn(fmaxf(h[2], 0.0f), fmaxf(h[3], 0.0f));
        __half2 p2 = __floats2half2_rn(fmaxf(h[4], 0.0f), fmaxf(h[5], 0.0f));
        __half2 p3 = __floats2half2_rn(fmaxf(h[6], 0.0f), fmaxf(h[7], 0.0f));
        uint4 st;
        st.x = reinterpret_cast<unsigned&>(p0);
        st.y = reinterpret_cast<unsigned&>(p1);
        st.z = reinterpret_cast<unsigned&>(p2);
        st.w = reinterpret_cast<unsigned&>(p3);
        *(uint4*)&g_H[(size_t)(r0 + r) * FFN + c0] = st;
    }
}

// ---------------------------------------------------------------------------
// Kernel 2: W2 -> fp16
// ---------------------------------------------------------------------------
__global__ void w_half_kernel(const float* __restrict__ W2) {
    int idx = blockIdx.x * blockDim.x + threadIdx.x;
    float2 v = ((const float2*)W2)[idx];
    ((__half2*)g_Wh)[idx] = __floats2half2_rn(v.x, v.y);
}

// ---------------------------------------------------------------------------
// Kernel 3: OUT = H @ W2^T + b2, mma.sync fp16 single pass, fp32 acc.
// CTA 128x128, BK=64, 4 warps (2x2, warp tile 64x64), 3-stage cp.async,
// 96KB dynamic smem, 2 CTAs/SM.  (R14-proven, byte-identical.)
// ---------------------------------------------------------------------------
#define BM 128
#define BN 128
#define BK 64
#define NT (FFN / BK)             // 32
#define STG 32768                 // A 0 (16384), B 16384 (16384)
#define SMEM_TOTAL (3 * STG)      // 98304

#define CP16(dst, src) \
    asm volatile("cp.async.cg.shared.global [%0], [%1], 16;\n" :: "r"(dst), "l"(src))

__device__ __forceinline__ void ldsm4(unsigned* r, unsigned a) {
    asm volatile("ldmatrix.sync.aligned.m8n8.x4.shared.b16 {%0,%1,%2,%3}, [%4];"
                 : "=r"(r[0]), "=r"(r[1]), "=r"(r[2]), "=r"(r[3]) : "r"(a));
}

__device__ __forceinline__ void mma16816(float* c, const unsigned* a, const unsigned* b) {
    asm volatile("mma.sync.aligned.m16n8k16.row.col.f32.f16.f16.f32 "
                 "{%0,%1,%2,%3}, {%4,%5,%6,%7}, {%8,%9}, {%0,%1,%2,%3};"
                 : "+f"(c[0]), "+f"(c[1]), "+f"(c[2]), "+f"(c[3])
                 : "r"(a[0]), "r"(a[1]), "r"(a[2]), "r"(a[3]), "r"(b[0]), "r"(b[1]));
}

// 128B rows, 8 chunks of 16B, full SW128 swizzle
__device__ __forceinline__ unsigned swz(int row, int ch) {
    return (unsigned)(row * 128 + ((ch ^ (row & 7)) << 4));
}

__device__ __forceinline__ void load_stage(unsigned st, int bm, int bn, int tid, int k0) {
#pragma unroll
    for (int i = 0; i < 8; i++) {               // A: 1024 chunks of 16B
        int id = tid + (i << 7);
        int r = id >> 3, c = id & 7;
        size_t g = (size_t)(bm + r) * FFN + k0 + c * 8;
        CP16(st + swz(r, c), g_H + g);
    }
#pragma unroll
    for (int i = 0; i < 8; i++) {               // B: 1024 chunks of 16B
        int id = tid + (i << 7);
        int r = id >> 3, c = id & 7;
        size_t g = (size_t)(bn + r) * FFN + k0 + c * 8;
        CP16(st + 16384 + swz(r, c), g_Wh + g);
    }
}

__global__ void __launch_bounds__(128, 2)
mma_gemm(const float* __restrict__ bias, float* __restrict__ C) {
    extern __shared__ __align__(128) unsigned char smem[];
    const int tid  = threadIdx.x;
    const int warp = tid >> 5, lane = tid & 31;
    const int wm = warp & 1;                 // 2 m-groups of 64 rows
    const int wn = warp >> 1;                // 2 n-groups of 64 cols
    const int bm = blockIdx.y * BM, bn = blockIdx.x * BN;
    const unsigned sbase = (unsigned)__cvta_generic_to_shared(smem);

    float acc[4][8][4];                      // [mf][nf][frag]
#pragma unroll
    for (int i = 0; i < 4; i++)
#pragma unroll
        for (int j = 0; j < 8; j++)
#pragma unroll
            for (int k = 0; k < 4; k++) acc[i][j][k] = 0.0f;

    load_stage(sbase,       bm, bn, tid, 0);
    asm volatile("cp.async.commit_group;\n");
    load_stage(sbase + STG, bm, bn, tid, BK);
    asm volatile("cp.async.commit_group;\n");

    for (int t = 0; t < NT; t++) {
        if (t + 1 < NT) asm volatile("cp.async.wait_group 1;\n" ::: "memory");
        else            asm volatile("cp.async.wait_group 0;\n" ::: "memory");
        __syncthreads();          // single barrier per stage (3-stage ring)

        if (t + 2 < NT) {
            load_stage(sbase + ((t + 2) % 3) * STG, bm, bn, tid, (t + 2) * BK);
            asm volatile("cp.async.commit_group;\n");
        }

        unsigned st = sbase + (t % 3) * STG;
#pragma unroll
        for (int kk = 0; kk < 4; kk++) {     // four k16 chunks of BK=64
            unsigned ah[4][4], bh[4][4];
#pragma unroll
            for (int mf = 0; mf < 4; mf++) {     // A frags: m64 x k16
                int r  = wm * 64 + mf * 16 + (lane & 15);
                int ch = kk * 2 + (lane >> 4);
                ldsm4(ah[mf], st + swz(r, ch));
            }
#pragma unroll
            for (int nb = 0; nb < 4; nb++) {     // B frags: n64
                int n  = wn * 64 + nb * 16 + (lane & 7) + ((lane >> 4) & 1) * 8;
                int ch = kk * 2 + ((lane >> 3) & 1);
                ldsm4(bh[nb], st + 16384 + swz(n, ch));
            }
#pragma unroll
            for (int mf = 0; mf < 4; mf++)
#pragma unroll
                for (int nf = 0; nf < 8; nf++)
                    mma16816(acc[mf][nf], ah[mf], &bh[nf >> 1][(nf & 1) * 2]);
        }
    }

    // epilogue: add bias
#pragma unroll
    for (int mf = 0; mf < 4; mf++) {
        int r0 = bm + wm * 64 + mf * 16 + (lane >> 2);
#pragma unroll
        for (int nf = 0; nf < 8; nf++) {
            int cc = bn + wn * 64 + nf * 8 + (lane & 3) * 2;
            float2 b2 = *(const float2*)&bias[cc];
            float2 v0 = make_float2(acc[mf][nf][0] + b2.x, acc[mf][nf][1] + b2.y);
            float2 v1 = make_float2(acc[mf][nf][2] + b2.x, acc[mf][nf][3] + b2.y);
            *(float2*)&C[(size_t)r0 * EMB + cc]       = v0;
            *(float2*)&C[(size_t)(r0 + 8) * EMB + cc] = v1;
        }
    }
}

// ---------------------------------------------------------------------------
extern "C" void kernel_launch(void* const* d_in, const int* in_sizes, int n_in,
                              void* d_out, int out_size) {
    const float* x      = (const float*)d_in[0];  // [16,2048,8]
    const float* params = (const float*)d_in[1];  // [8,3]
    const float* W1     = (const float*)d_in[2];  // [2048,8]
    const float* b1     = (const float*)d_in[3];  // [2048]
    const float* W2     = (const float*)d_in[4];  // [512,2048]
    const float* b2     = (const float*)d_in[5];  // [512]
    float* out = (float*)d_out;                   // [16,2048,512]

    cudaFuncSetAttribute(mma_gemm, cudaFuncAttributeMaxDynamicSharedMemorySize,
                         SMEM_TOTAL);

    w_half_kernel<<<(EMB * (FFN / 2)) / 256, 256>>>(W2);
    h_fused_kernel<<<NROWS / HROWS, 256>>>(x, params, W1, b1);
    mma_gemm<<<dim3(EMB / BN, NROWS / BM), 128, SMEM_TOTAL>>>(b2, out);
}

// round 16
// speedup vs baseline: 1.4094x; 1.0076x over previous
#include <cuda_runtime.h>
#include <cuda_fp16.h>
#include <math.h>
#include <stdint.h>

#define NROWS 32768      // B*S
#define FFN   2048
#define EMB   512

// ---------------- scratch ---------------------------------------------------
__device__ __half g_H[(size_t)NROWS * FFN];        // 128 MB (fp16 of H)
__device__ __half g_Wh[EMB * FFN];                 // 2 MB  (fp16 of W2)

// ---------------------------------------------------------------------------
// Kernel 1 (fused): EV (closed-form circuit) + H = relu(EV@W1^T+b1) -> fp16,
// plus grid-strided W2 -> fp16 conversion (hidden under the EV/store phases).
// One block owns 64 rows x ALL 2048 columns; EV in smem; W1 in regs.
// ---------------------------------------------------------------------------
#define HROWS 64
__global__ void __launch_bounds__(256)
h_fused_kernel(const float* __restrict__ x, const float* __restrict__ params,
               const float* __restrict__ W1, const float* __restrict__ b1,
               const float* __restrict__ W2) {
    __shared__ float sA[8], sC[8];
    __shared__ float sEV[HROWS][8];
    const int tid = threadIdx.x;
    const int r0  = blockIdx.x * HROWS;

    // --- folded W2 -> fp16: 524288 float2 pairs over 131072 threads (4 each)
    {
        int g = blockIdx.x * 256 + tid;          // 0 .. 131071
#pragma unroll
        for (int i = 0; i < 4; i++) {
            int idx = g + (i << 17);             // stride 131072
            float2 v = ((const float2*)W2)[idx];
            ((__half2*)g_Wh)[idx] = __floats2half2_rn(v.x, v.y);
        }
    }

    if (tid < 8) {
        float a = params[tid * 3 + 0];
        float b = params[tid * 3 + 1];
        float c = params[tid * 3 + 2];
        float sa, ca, sb, cb, sc, cc;
        sincosf(a, &sa, &ca);
        sincosf(b, &sb, &cb);
        sincosf(c, &sc, &cc);
        sA[tid] = ca * cc + sa * sb * sc;
        sC[tid] = cb * sc;
    }
    __syncthreads();

    if (tid < HROWS) {
        int row = r0 + tid;
        float z[8];
#pragma unroll
        for (int i = 0; i < 8; i++) {
            float sx, cx;
            sincosf(x[row * 8 + i], &sx, &cx);
            z[i] = sA[i] * cx - sC[i] * sx;
        }
        float ev[8];
        float pre = z[0];
#pragma unroll
        for (int k = 1; k < 8; k++) { pre *= z[k]; ev[k] = pre; }
        float suf = 1.0f;
#pragma unroll
        for (int k = 7; k >= 1; k--) suf *= z[k];
        ev[0] = suf;
#pragma unroll
        for (int k = 0; k < 8; k++) sEV[tid][k] = ev[k];
    }

    // W1 for this thread's 8 columns, cached in registers
    const int c0 = tid * 8;
    float4 w0[8], w1[8];
    float bb[8];
#pragma unroll
    for (int j = 0; j < 8; j++) {
        w0[j] = *(const float4*)&W1[(c0 + j) * 8];
        w1[j] = *(const float4*)&W1[(c0 + j) * 8 + 4];
        bb[j] = b1[c0 + j];
    }
    __syncthreads();

#pragma unroll 2
    for (int r = 0; r < HROWS; r++) {
        float4 e0 = *(const float4*)&sEV[r][0];
        float4 e1 = *(const float4*)&sEV[r][4];
        float h[8];
#pragma unroll
        for (int j = 0; j < 8; j++) {
            h[j] = bb[j]
                 + e0.x * w0[j].x + e0.y * w0[j].y + e0.z * w0[j].z + e0.w * w0[j].w
                 + e1.x * w1[j].x + e1.y * w1[j].y + e1.z * w1[j].z + e1.w * w1[j].w;
        }
        __half2 p0 = __floats2half2_rn(fmaxf(h[0], 0.0f), fmaxf(h[1], 0.0f));
        __half2 p1 = __floats2half2_rn(fmaxf(h[2], 0.0f), fmaxf(h[3], 0.0f));
        __half2 p2 = __floats2half2_rn(fmaxf(h[4], 0.0f), fmaxf(h[5], 0.0f));
        __half2 p3 = __floats2half2_rn(fmaxf(h[6], 0.0f), fmaxf(h[7], 0.0f));
        uint4 st;
        st.x = reinterpret_cast<unsigned&>(p0);
        st.y = reinterpret_cast<unsigned&>(p1);
        st.z = reinterpret_cast<unsigned&>(p2);
        st.w = reinterpret_cast<unsigned&>(p3);
        *(uint4*)&g_H[(size_t)(r0 + r) * FFN + c0] = st;
    }
}

// ---------------------------------------------------------------------------
// Kernel 2: OUT = H @ W2^T + b2, mma.sync fp16 single pass, fp32 acc.
// CTA 128x128, BK=64, 4 warps (2x2, warp tile 64x64), 3-stage cp.async,
// 96KB dynamic smem, 2 CTAs/SM.  (R14-proven, byte-identical.)
// ---------------------------------------------------------------------------
#define BM 128
#define BN 128
#define BK 64
#define NT (FFN / BK)             // 32
#define STG 32768                 // A 0 (16384), B 16384 (16384)
#define SMEM_TOTAL (3 * STG)      // 98304

#define CP16(dst, src) \
    asm volatile("cp.async.cg.shared.global [%0], [%1], 16;\n" :: "r"(dst), "l"(src))

__device__ __forceinline__ void ldsm4(unsigned* r, unsigned a) {
    asm volatile("ldmatrix.sync.aligned.m8n8.x4.shared.b16 {%0,%1,%2,%3}, [%4];"
                 : "=r"(r[0]), "=r"(r[1]), "=r"(r[2]), "=r"(r[3]) : "r"(a));
}

__device__ __forceinline__ void mma16816(float* c, const unsigned* a, const unsigned* b) {
    asm volatile("mma.sync.aligned.m16n8k16.row.col.f32.f16.f16.f32 "
                 "{%0,%1,%2,%3}, {%4,%5,%6,%7}, {%8,%9}, {%0,%1,%2,%3};"
                 : "+f"(c[0]), "+f"(c[1]), "+f"(c[2]), "+f"(c[3])
                 : "r"(a[0]), "r"(a[1]), "r"(a[2]), "r"(a[3]), "r"(b[0]), "r"(b[1]));
}

// 128B rows, 8 chunks of 16B, full SW128 swizzle
__device__ __forceinline__ unsigned swz(int row, int ch) {
    return (unsigned)(row * 128 + ((ch ^ (row & 7)) << 4));
}

__device__ __forceinline__ void load_stage(unsigned st, int bm, int bn, int tid, int k0) {
#pragma unroll
    for (int i = 0; i < 8; i++) {               // A: 1024 chunks of 16B
        int id = tid + (i << 7);
        int r = id >> 3, c = id & 7;
        size_t g = (size_t)(bm + r) * FFN + k0 + c * 8;
        CP16(st + swz(r, c), g_H + g);
    }
#pragma unroll
    for (int i = 0; i < 8; i++) {               // B: 1024 chunks of 16B
        int id = tid + (i << 7);
        int r = id >> 3, c = id & 7;
        size_t g = (size_t)(bn + r) * FFN + k0 + c * 8;
        CP16(st + 16384 + swz(r, c), g_Wh + g);
    }
}

__global__ void __launch_bounds__(128, 2)
mma_gemm(const float* __restrict__ bias, float* __restrict__ C) {
    extern __shared__ __align__(128) unsigned char smem[];
    const int tid  = threadIdx.x;
    const int warp = tid >> 5, lane = tid & 31;
    const int wm = warp & 1;                 // 2 m-groups of 64 rows
    const int wn = warp >> 1;                // 2 n-groups of 64 cols
    const int bm = blockIdx.y * BM, bn = blockIdx.x * BN;
    const unsigned sbase = (unsigned)__cvta_generic_to_shared(smem);

    float acc[4][8][4];                      // [mf][nf][frag]
#pragma unroll
    for (int i = 0; i < 4; i++)
#pragma unroll
        for (int j = 0; j < 8; j++)
#pragma unroll
            for (int k = 0; k < 4; k++) acc[i][j][k] = 0.0f;

    load_stage(sbase,       bm, bn, tid, 0);
    asm volatile("cp.async.commit_group;\n");
    load_stage(sbase + STG, bm, bn, tid, BK);
    asm volatile("cp.async.commit_group;\n");

    for (int t = 0; t < NT; t++) {
        if (t + 1 < NT) asm volatile("cp.async.wait_group 1;\n" ::: "memory");
        else            asm volatile("cp.async.wait_group 0;\n" ::: "memory");
        __syncthreads();          // single barrier per stage (3-stage ring)

        if (t + 2 < NT) {
            load_stage(sbase + ((t + 2) % 3) * STG, bm, bn, tid, (t + 2) * BK);
            asm volatile("cp.async.commit_group;\n");
        }

        unsigned st = sbase + (t % 3) * STG;
#pragma unroll
        for (int kk = 0; kk < 4; kk++) {     // four k16 chunks of BK=64
            unsigned ah[4][4], bh[4][4];
#pragma unroll
            for (int mf = 0; mf < 4; mf++) {     // A frags: m64 x k16
                int r  = wm * 64 + mf * 16 + (lane & 15);
                int ch = kk * 2 + (lane >> 4);
                ldsm4(ah[mf], st + swz(r, ch));
            }
#pragma unroll
            for (int nb = 0; nb < 4; nb++) {     // B frags: n64
                int n  = wn * 64 + nb * 16 + (lane & 7) + ((lane >> 4) & 1) * 8;
                int ch = kk * 2 + ((lane >> 3) & 1);
                ldsm4(bh[nb], st + 16384 + swz(n, ch));
            }
#pragma unroll
            for (int mf = 0; mf < 4; mf++)
#pragma unroll
                for (int nf = 0; nf < 8; nf++)
                    mma16816(acc[mf][nf], ah[mf], &bh[nf >> 1][(nf & 1) * 2]);
        }
    }

    // epilogue: add bias
#pragma unroll
    for (int mf = 0; mf < 4; mf++) {
        int r0 = bm + wm * 64 + mf * 16 + (lane >> 2);
#pragma unroll
        for (int nf = 0; nf < 8; nf++) {
            int cc = bn + wn * 64 + nf * 8 + (lane & 3) * 2;
            float2 b2 = *(const float2*)&bias[cc];
            float2 v0 = make_float2(acc[mf][nf][0] + b2.x, acc[mf][nf][1] + b2.y);
            float2 v1 = make_float2(acc[mf][nf][2] + b2.x, acc[mf][nf][3] + b2.y);
            *(float2*)&C[(size_t)r0 * EMB + cc]       = v0;
            *(float2*)&C[(size_t)(r0 + 8) * EMB + cc] = v1;
        }
    }
}

// ---------------------------------------------------------------------------
extern "C" void kernel_launch(void* const* d_in, const int* in_sizes, int n_in,
                              void* d_out, int out_size) {
    const float* x      = (const float*)d_in[0];  // [16,2048,8]
    const float* params = (const float*)d_in[1];  // [8,3]
    const float* W1     = (const float*)d_in[2];  // [2048,8]
    const float* b1     = (const float*)d_in[3];  // [2048]
    const float* W2     = (const float*)d_in[4];  // [512,2048]
    const float* b2     = (const float*)d_in[5];  // [512]
    float* out = (float*)d_out;                   // [16,2048,512]

    cudaFuncSetAttribute(mma_gemm, cudaFuncAttributeMaxDynamicSharedMemorySize,
                         SMEM_TOTAL);

    h_fused_kernel<<<NROWS / HROWS, 256>>>(x, params, W1, b1, W2);
    mma_gemm<<<dim3(EMB / BN, NROWS / BM), 128, SMEM_TOTAL>>>(b2, out);
}